// round 7
// baseline (speedup 1.0000x reference)
#include <cuda_runtime.h>

// Problem constants (fixed by setup_inputs)
#define N_PTS 2048
#define N_C   1024
#define B_SZ  8
#define BLOCK_THREADS 1024
#define PTS_PER_BLOCK 1024
#define BLOCKS_PER_BATCH 2
#define NUM_BLOCKS (B_SZ * BLOCKS_PER_BATCH)       // 16
#define N_TOTAL (B_SZ * N_PTS)                     // 16384
#define NB 1024                                    // bins per batch
#define XMIN_F (-4.5f)
#define XRANGE_F (9.0f)

// Output layout (tuple concat): y_diff | x_diff | d_out(B,N,2) | x_n | y_n
#define OFF_YDIFF 0
#define OFF_XDIFF (N_TOTAL)
#define OFF_DOUT  (2 * N_TOTAL)
#define OFF_XN    (4 * N_TOTAL)
#define OFF_YN    (5 * N_TOTAL)

__device__ double g_psum[NUM_BLOCKS];
__device__ double g_psum2[NUM_BLOCKS];
__device__ int    g_count = 0;

typedef unsigned long long ull;

static __device__ __forceinline__ int bin_of(float v) {
    int t = (int)((v - XMIN_F) * ((float)NB / XRANGE_F));
    t = t < 0 ? 0 : t;
    return t > (NB - 1) ? (NB - 1) : t;
}

__global__ __launch_bounds__(BLOCK_THREADS) void nn_bin_kernel(
    const float* __restrict__ y, const float* __restrict__ x,
    const float* __restrict__ bn_w, const float* __restrict__ bn_b,
    float* __restrict__ out)
{
    __shared__ float  sx[N_PTS];
    __shared__ float  sy[N_PTS];
    __shared__ float2 bpt[N_PTS];            // (x value, idx-as-float-bits) in bin order
    __shared__ int    binCnt[NB];
    __shared__ int    binStart[NB + 1];
    __shared__ int    binFill[NB];
    __shared__ double s_ws[32], s_ws2[32];   // per-warp partials
    __shared__ double s_fin[2];
    __shared__ float  s_affine[2];
    __shared__ int    s_islast;

    const int tid   = threadIdx.x;
    const int wid   = tid >> 5;
    const int lane  = tid & 31;
    const int batch = blockIdx.x >> 1;                 // / BLOCKS_PER_BATCH
    const int base  = (blockIdx.x & 1) * PTS_PER_BLOCK;

    const float width = XRANGE_F / (float)NB;

    // ---- Load batch into SMEM (vectorized; 1 float4 iter per thread per array) ----
    {
        const float4* xb4 = (const float4*)(x + batch * N_PTS);
        const float4* yb4 = (const float4*)(y + batch * N_PTS);
        float4* sxv = (float4*)sx;
        float4* syv = (float4*)sy;
        if (tid < N_PTS / 4) {
            sxv[tid] = xb4[tid];
            syv[tid] = yb4[tid];
        }
    }
    if (tid < NB) binCnt[tid] = 0;
    __syncthreads();                                   // B1

    // ---- Histogram (2 points per thread) ----
    {
        const float v0 = sx[tid];
        const float v1 = sx[tid + 1024];
        atomicAdd(&binCnt[bin_of(v0)], 1);
        atomicAdd(&binCnt[bin_of(v1)], 1);
    }
    __syncthreads();                                   // B2

    // ---- Exclusive scan over NB bins by warp 0 (32 bins per lane) ----
    if (wid == 0) {
        const int b0 = lane * (NB / 32);
        int c[NB / 32];
        int run = 0;
        #pragma unroll
        for (int k = 0; k < NB / 32; ++k) {
            c[k] = run;
            run += binCnt[b0 + k];
        }
        // exclusive shuffle scan of lane totals
        int v = run;
        #pragma unroll
        for (int off = 1; off < 32; off <<= 1) {
            int n = __shfl_up_sync(0xffffffffu, v, off);
            if (lane >= off) v += n;
        }
        const int pre = v - run;
        #pragma unroll
        for (int k = 0; k < NB / 32; ++k) {
            const int s = pre + c[k];
            binStart[b0 + k] = s;
            binFill[b0 + k]  = s;
        }
        if (lane == 31) binStart[NB] = pre + run;      // == N_PTS
    }
    __syncthreads();                                   // B3

    // ---- Scatter (counting sort by bin; order within bin arbitrary — keys fix it) ----
    {
        const float v0 = sx[tid];
        const float v1 = sx[tid + 1024];
        int pos = atomicAdd(&binFill[bin_of(v0)], 1);
        bpt[pos] = make_float2(v0, __int_as_float(tid));
        pos = atomicAdd(&binFill[bin_of(v1)], 1);
        bpt[pos] = make_float2(v1, __int_as_float(tid + 1024));
    }
    __syncthreads();                                   // B4

    // ---- Per-thread NN search over expanding bin window ----
    const int   p     = base + tid;                    // point index within batch
    const int   limit = (p < N_C) ? (N_C - 1) : p;     // valid candidate: j <= limit
    const float xi    = sx[p];

    // top-2 by exact key = (bits(sqrt_rn(dx*dx)) << 32) | j ; init to (+inf, maxidx)
    const ull KEY_INF = ((ull)0x7f800000u << 32) | 0xffffffffu;
    ull k1 = KEY_INF, k2 = KEY_INF;

    const int t0 = bin_of(xi);

    #define SCAN_BIN(T)                                                        \
        {                                                                      \
            const int qe = binStart[(T) + 1];                                  \
            for (int q = binStart[(T)]; q < qe; ++q) {                         \
                const float2 pr = bpt[q];                                      \
                const int j = __float_as_int(pr.y);                            \
                if (j <= limit) {                                              \
                    const float dx   = xi - pr.x;                              \
                    const float dist = __fsqrt_rn(__fmul_rn(dx, dx));          \
                    const ull key = ((ull)__float_as_uint(dist) << 32)         \
                                    | (unsigned int)j;                         \
                    if (key < k1)      { k2 = k1; k1 = key; }                  \
                    else if (key < k2) { k2 = key; }                           \
                }                                                              \
            }                                                                  \
        }

    SCAN_BIN(t0);
    {
        int l = t0 - 1, r = t0 + 1;
        while (true) {
            const float d2v = __uint_as_float((unsigned int)(k2 >> 32)); // +inf until 2 found
            // conservative cushion: covers bin-edge rounding + sqrt rounding ties
            const float thr = d2v + (width * 1e-3f + d2v * 1e-5f);
            const float bl = (l >= 0) ? fmaxf(xi - (XMIN_F + (float)(l + 1) * width), 0.0f)
                                      : __int_as_float(0x7f800000);
            const float br = (r < NB) ? fmaxf((XMIN_F + (float)r * width) - xi, 0.0f)
                                      : __int_as_float(0x7f800000);
            const bool canL = (l >= 0) && (bl <= thr);
            const bool canR = (r < NB) && (br <= thr);
            if (!canL && !canR) break;
            if (canL && (!canR || bl <= br)) { SCAN_BIN(l); --l; }
            else                             { SCAN_BIN(r); ++r; }
        }
    }
    #undef SCAN_BIN

    // ---- Derivative + outputs ----
    float d2out;
    {
        const int nn = (int)(unsigned int)(k2 & 0xffffffffULL);  // argsort[...,1]
        const float xcl  = sx[nn];
        const float ycl  = sy[nn];
        const float xrep = xi - xcl;
        const float yrep = sy[p] - ycl;
        const float nrm  = __fsqrt_rn(__fmul_rn(xrep, xrep));
        const float d    = __fdiv_rn(yrep, __fadd_rn(2e-6f, nrm));
        const bool  clip = (fabsf(d) > 200.0f);
        d2out = clip ? 0.0f : d;
        const float lab = clip ? 0.0f : 1.0f;

        const int g = batch * N_PTS + p;
        out[OFF_YDIFF + g]        = yrep;
        out[OFF_XDIFF + g]        = xrep;
        out[OFF_DOUT + 2 * g]     = d2out;   // raw; normalized in-place below
        out[OFF_DOUT + 2 * g + 1] = lab;
        out[OFF_XN + g]           = xcl;
        out[OFF_YN + g]           = ycl;
    }

    // ---- Deterministic partial sums: warp shuffle (fixed order) + warp0 combine ----
    {
        double s  = (double)d2out;
        double s2 = s * s;
        #pragma unroll
        for (int off = 16; off > 0; off >>= 1) {
            s  += __shfl_down_sync(0xffffffffu, s,  off);
            s2 += __shfl_down_sync(0xffffffffu, s2, off);
        }
        if (lane == 0) { s_ws[wid] = s; s_ws2[wid] = s2; }
    }
    __syncthreads();                                   // B5
    if (wid == 0) {
        double s  = s_ws[lane];
        double s2 = s_ws2[lane];
        #pragma unroll
        for (int off = 16; off > 0; off >>= 1) {
            s  += __shfl_down_sync(0xffffffffu, s,  off);
            s2 += __shfl_down_sync(0xffffffffu, s2, off);
        }
        if (lane == 0) {
            g_psum[blockIdx.x]  = s;
            g_psum2[blockIdx.x] = s2;
            __threadfence();
            const int old = atomicAdd(&g_count, 1);
            s_islast = (old == NUM_BLOCKS - 1);
        }
    }
    __syncthreads();                                   // B6

    if (!s_islast) return;

    // ---- Last block: final reduce + affine + in-place normalize ----
    __threadfence();  // acquire all other blocks' out[] and psum writes

    if (tid == 0) {
        double s = 0.0, s2 = 0.0;
        #pragma unroll
        for (int i = 0; i < NUM_BLOCKS; ++i) {
            s  += g_psum[i];
            s2 += g_psum2[i];
        }
        s_fin[0] = s;
        s_fin[1] = s2;
        const double n    = (double)N_TOTAL;
        const double mean = s / n;
        const double var  = s2 / n - mean * mean;
        const double invs = 1.0 / sqrt(var + 1e-5);
        const float scale = (float)invs * bn_w[0];
        s_affine[0] = scale;
        s_affine[1] = bn_b[0] - (float)mean * scale;
        g_count = 0;   // reset for next graph replay
    }
    __syncthreads();                                   // B7

    const float scale = s_affine[0];
    const float shift = s_affine[1];
    #pragma unroll
    for (int g = tid; g < N_TOTAL; g += BLOCK_THREADS) {
        const int idx = OFF_DOUT + 2 * g;
        out[idx] = fmaf(out[idx], scale, shift);
    }
}

extern "C" void kernel_launch(void* const* d_in, const int* in_sizes, int n_in,
                              void* d_out, int out_size) {
    const float* y    = (const float*)d_in[0];
    const float* x    = (const float*)d_in[1];
    const float* bn_w = (const float*)d_in[2];
    const float* bn_b = (const float*)d_in[3];
    float* out = (float*)d_out;

    nn_bin_kernel<<<NUM_BLOCKS, BLOCK_THREADS>>>(y, x, bn_w, bn_b, out);
}

// round 8
// speedup vs baseline: 1.4091x; 1.4091x over previous
#include <cuda_runtime.h>

// Problem constants (fixed by setup_inputs)
#define N_PTS 2048
#define N_C   1024
#define B_SZ  8
#define BLOCK_THREADS 256
#define PTS_PER_BLOCK 256
#define BLOCKS_PER_BATCH (N_PTS / PTS_PER_BLOCK)   // 8
#define NUM_BLOCKS (B_SZ * BLOCKS_PER_BATCH)       // 64
#define N_TOTAL (B_SZ * N_PTS)                     // 16384
#define NB 512                                     // bins per batch
#define XMIN_F (-4.5f)
#define XRANGE_F (9.0f)

// Output layout (tuple concat): y_diff | x_diff | d_out(B,N,2) | x_n | y_n
#define OFF_YDIFF 0
#define OFF_XDIFF (N_TOTAL)
#define OFF_DOUT  (2 * N_TOTAL)
#define OFF_XN    (4 * N_TOTAL)
#define OFF_YN    (5 * N_TOTAL)

__device__ double g_psum[NUM_BLOCKS];
__device__ double g_psum2[NUM_BLOCKS];
__device__ int    g_count = 0;

typedef unsigned long long ull;

static __device__ __forceinline__ int bin_of(float v) {
    int t = (int)((v - XMIN_F) * ((float)NB / XRANGE_F));
    t = t < 0 ? 0 : t;
    return t > (NB - 1) ? (NB - 1) : t;
}

__global__ __launch_bounds__(BLOCK_THREADS) void nn_bin_kernel(
    const float* __restrict__ y, const float* __restrict__ x,
    const float* __restrict__ bn_w, const float* __restrict__ bn_b,
    float* __restrict__ out)
{
    __shared__ float  sx[N_PTS];
    __shared__ float  sy[N_PTS];
    __shared__ float2 bpt[N_PTS];            // (x value, idx bits) in bin order
    __shared__ int    binCnt[NB];
    __shared__ int    binStart[NB + 1];
    __shared__ int    binFill[NB];
    __shared__ double s_ws[8], s_ws2[8];
    __shared__ float  s_affine[2];
    __shared__ int    s_islast;

    const int tid   = threadIdx.x;
    const int wid   = tid >> 5;
    const int lane  = tid & 31;
    const int batch = blockIdx.x >> 3;                 // / BLOCKS_PER_BATCH
    const int base  = (blockIdx.x & 7) * PTS_PER_BLOCK;

    const float width = XRANGE_F / (float)NB;

    // ---- Load batch into SMEM (vectorized) + zero histogram ----
    {
        const float4* xb4 = (const float4*)(x + batch * N_PTS);
        const float4* yb4 = (const float4*)(y + batch * N_PTS);
        float4* sxv = (float4*)sx;
        float4* syv = (float4*)sy;
        #pragma unroll
        for (int i = tid; i < N_PTS / 4; i += BLOCK_THREADS) {
            sxv[i] = xb4[i];
            syv[i] = yb4[i];
        }
    }
    #pragma unroll
    for (int i = tid; i < NB; i += BLOCK_THREADS) binCnt[i] = 0;
    __syncthreads();                                   // B1

    // ---- Histogram (8 points per thread) ----
    #pragma unroll
    for (int i = tid; i < N_PTS; i += BLOCK_THREADS)
        atomicAdd(&binCnt[bin_of(sx[i])], 1);
    __syncthreads();                                   // B2

    // ---- Exclusive scan over NB=512 bins by warp 0 (16 bins/lane, shuffle scan) ----
    if (wid == 0) {
        const int b0 = lane * (NB / 32);
        int c[NB / 32];
        int run = 0;
        #pragma unroll
        for (int k = 0; k < NB / 32; ++k) {
            c[k] = run;
            run += binCnt[b0 + k];
        }
        int v = run;
        #pragma unroll
        for (int off = 1; off < 32; off <<= 1) {
            int n = __shfl_up_sync(0xffffffffu, v, off);
            if (lane >= off) v += n;
        }
        const int pre = v - run;
        #pragma unroll
        for (int k = 0; k < NB / 32; ++k) {
            const int s = pre + c[k];
            binStart[b0 + k] = s;
            binFill[b0 + k]  = s;
        }
        if (lane == 31) binStart[NB] = pre + run;      // == N_PTS
    }
    __syncthreads();                                   // B3

    // ---- Scatter (counting sort by bin; in-bin order arbitrary — keys fix it) ----
    #pragma unroll
    for (int i = tid; i < N_PTS; i += BLOCK_THREADS) {
        const float v = sx[i];
        const int pos = atomicAdd(&binFill[bin_of(v)], 1);
        bpt[pos] = make_float2(v, __int_as_float(i));
    }
    __syncthreads();                                   // B4

    // ---- Per-thread NN search over expanding bin window ----
    const int   p     = base + tid;                    // point index within batch
    const int   limit = (p < N_C) ? (N_C - 1) : p;     // valid candidate: j <= limit
    const float xi    = sx[p];

    // top-2 by exact key = (bits(sqrt_rn(dx*dx)) << 32) | j ; init (+inf, maxidx)
    const ull KEY_INF = ((ull)0x7f800000u << 32) | 0xffffffffu;
    ull k1 = KEY_INF, k2 = KEY_INF;

    const int t0 = bin_of(xi);

    #define SCAN_BIN(T)                                                        \
        {                                                                      \
            const int qe = binStart[(T) + 1];                                  \
            for (int q = binStart[(T)]; q < qe; ++q) {                         \
                const float2 pr = bpt[q];                                      \
                const int j = __float_as_int(pr.y);                            \
                if (j <= limit) {                                              \
                    const float dx   = xi - pr.x;                              \
                    const float dist = __fsqrt_rn(__fmul_rn(dx, dx));          \
                    const ull key = ((ull)__float_as_uint(dist) << 32)         \
                                    | (unsigned int)j;                         \
                    if (key < k1)      { k2 = k1; k1 = key; }                  \
                    else if (key < k2) { k2 = key; }                           \
                }                                                              \
            }                                                                  \
        }

    SCAN_BIN(t0);
    {
        int l = t0 - 1, r = t0 + 1;
        while (true) {
            const float d2v = __uint_as_float((unsigned int)(k2 >> 32)); // +inf until 2 found
            // conservative cushion: covers bin-edge rounding + sqrt rounding ties
            const float thr = d2v + (width * 1e-3f + d2v * 1e-5f);
            const float bl = (l >= 0) ? fmaxf(xi - (XMIN_F + (float)(l + 1) * width), 0.0f)
                                      : __int_as_float(0x7f800000);
            const float br = (r < NB) ? fmaxf((XMIN_F + (float)r * width) - xi, 0.0f)
                                      : __int_as_float(0x7f800000);
            const bool canL = (l >= 0) && (bl <= thr);
            const bool canR = (r < NB) && (br <= thr);
            if (!canL && !canR) break;
            if (canL && (!canR || bl <= br)) { SCAN_BIN(l); --l; }
            else                             { SCAN_BIN(r); ++r; }
        }
    }
    #undef SCAN_BIN

    // ---- Derivative + outputs ----
    float d2out;
    {
        const int nn = (int)(unsigned int)(k2 & 0xffffffffULL);  // argsort[...,1]
        const float xcl  = sx[nn];
        const float ycl  = sy[nn];
        const float xrep = xi - xcl;
        const float yrep = sy[p] - ycl;
        const float nrm  = __fsqrt_rn(__fmul_rn(xrep, xrep));
        const float d    = __fdiv_rn(yrep, __fadd_rn(2e-6f, nrm));
        const bool  clip = (fabsf(d) > 200.0f);
        d2out = clip ? 0.0f : d;
        const float lab = clip ? 0.0f : 1.0f;

        const int g = batch * N_PTS + p;
        out[OFF_YDIFF + g]        = yrep;
        out[OFF_XDIFF + g]        = xrep;
        out[OFF_DOUT + 2 * g]     = d2out;   // raw; normalized in-place below
        out[OFF_DOUT + 2 * g + 1] = lab;
        out[OFF_XN + g]           = xcl;
        out[OFF_YN + g]           = ycl;
    }

    // ---- Deterministic partial sums: warp shuffle (fixed order) + warp0 combine ----
    {
        double s  = (double)d2out;
        double s2 = s * s;
        #pragma unroll
        for (int off = 16; off > 0; off >>= 1) {
            s  += __shfl_down_sync(0xffffffffu, s,  off);
            s2 += __shfl_down_sync(0xffffffffu, s2, off);
        }
        if (lane == 0) { s_ws[wid] = s; s_ws2[wid] = s2; }
    }
    __syncthreads();                                   // B5
    if (tid == 0) {
        double s = 0.0, s2 = 0.0;
        #pragma unroll
        for (int w = 0; w < 8; ++w) { s += s_ws[w]; s2 += s_ws2[w]; }
        g_psum[blockIdx.x]  = s;
        g_psum2[blockIdx.x] = s2;
        __threadfence();
        const int old = atomicAdd(&g_count, 1);
        s_islast = (old == NUM_BLOCKS - 1);
    }
    __syncthreads();                                   // B6

    if (!s_islast) return;

    // ---- Last block: final reduce + affine + in-place normalize ----
    __threadfence();  // acquire all other blocks' out[] and psum writes

    {
        // 64 partials: lane-parallel load, shuffle reduce (fixed order, deterministic)
        double s = 0.0, s2 = 0.0;
        if (wid == 0) {
            s  = g_psum[lane]  + g_psum[lane + 32];
            s2 = g_psum2[lane] + g_psum2[lane + 32];
            #pragma unroll
            for (int off = 16; off > 0; off >>= 1) {
                s  += __shfl_down_sync(0xffffffffu, s,  off);
                s2 += __shfl_down_sync(0xffffffffu, s2, off);
            }
            if (lane == 0) {
                const double n    = (double)N_TOTAL;
                const double mean = s / n;
                const double var  = s2 / n - mean * mean;
                const double invs = 1.0 / sqrt(var + 1e-5);
                const float scale = (float)invs * bn_w[0];
                s_affine[0] = scale;
                s_affine[1] = bn_b[0] - (float)mean * scale;
                g_count = 0;   // reset for next graph replay
            }
        }
    }
    __syncthreads();                                   // B7

    const float scale = s_affine[0];
    const float shift = s_affine[1];
    #pragma unroll
    for (int g = tid; g < N_TOTAL; g += BLOCK_THREADS) {
        const int idx = OFF_DOUT + 2 * g;
        out[idx] = fmaf(out[idx], scale, shift);
    }
}

extern "C" void kernel_launch(void* const* d_in, const int* in_sizes, int n_in,
                              void* d_out, int out_size) {
    const float* y    = (const float*)d_in[0];
    const float* x    = (const float*)d_in[1];
    const float* bn_w = (const float*)d_in[2];
    const float* bn_b = (const float*)d_in[3];
    float* out = (float*)d_out;

    nn_bin_kernel<<<NUM_BLOCKS, BLOCK_THREADS>>>(y, x, bn_w, bn_b, out);
}

// round 9
// speedup vs baseline: 1.6518x; 1.1722x over previous
#include <cuda_runtime.h>

// Problem constants (fixed by setup_inputs)
#define N_PTS 2048
#define N_C   1024
#define B_SZ  8
#define BLOCK_THREADS 256
#define PTS_PER_BLOCK 256
#define BLOCKS_PER_BATCH (N_PTS / PTS_PER_BLOCK)   // 8
#define NUM_BLOCKS (B_SZ * BLOCKS_PER_BATCH)       // 64
#define N_TOTAL (B_SZ * N_PTS)                     // 16384
#define NB 512                                     // bins per batch
#define XMIN_F (-4.5f)
#define XRANGE_F (9.0f)
#define N_PSUM (NUM_BLOCKS * 8)                    // 512 per-warp partials

// Output layout (tuple concat): y_diff | x_diff | d_out(B,N,2) | x_n | y_n
#define OFF_YDIFF 0
#define OFF_XDIFF (N_TOTAL)
#define OFF_DOUT  (2 * N_TOTAL)
#define OFF_XN    (4 * N_TOTAL)
#define OFF_YN    (5 * N_TOTAL)

__device__ double g_psum[N_PSUM];
__device__ double g_psum2[N_PSUM];

typedef unsigned long long ull;

static __device__ __forceinline__ int bin_of(float v) {
    int t = (int)((v - XMIN_F) * ((float)NB / XRANGE_F));
    t = t < 0 ? 0 : t;
    return t > (NB - 1) ? (NB - 1) : t;
}

// ---------------- Kernel A: binned NN + derivative + outputs + warp psums ----
__global__ __launch_bounds__(BLOCK_THREADS) void nn_bin_kernel(
    const float* __restrict__ y, const float* __restrict__ x,
    float* __restrict__ out)
{
    __shared__ float  sx[N_PTS];
    __shared__ float  sy[N_PTS];
    __shared__ float2 bpt[N_PTS];            // (x value, idx bits) in bin order
    __shared__ int    binCnt[NB];
    __shared__ int    binStart[NB + 1];
    __shared__ int    binFill[NB];

    const int tid   = threadIdx.x;
    const int wid   = tid >> 5;
    const int lane  = tid & 31;
    const int batch = blockIdx.x >> 3;                 // / BLOCKS_PER_BATCH
    const int base  = (blockIdx.x & 7) * PTS_PER_BLOCK;

    const float width = XRANGE_F / (float)NB;

    // ---- Load batch into SMEM (vectorized) + zero histogram ----
    {
        const float4* xb4 = (const float4*)(x + batch * N_PTS);
        const float4* yb4 = (const float4*)(y + batch * N_PTS);
        float4* sxv = (float4*)sx;
        float4* syv = (float4*)sy;
        #pragma unroll
        for (int i = tid; i < N_PTS / 4; i += BLOCK_THREADS) {
            sxv[i] = xb4[i];
            syv[i] = yb4[i];
        }
    }
    #pragma unroll
    for (int i = tid; i < NB; i += BLOCK_THREADS) binCnt[i] = 0;
    __syncthreads();                                   // B1

    // ---- Histogram (8 points per thread) ----
    #pragma unroll
    for (int i = tid; i < N_PTS; i += BLOCK_THREADS)
        atomicAdd(&binCnt[bin_of(sx[i])], 1);
    __syncthreads();                                   // B2

    // ---- Exclusive scan over NB=512 bins by warp 0 (16 bins/lane, shuffle scan) ----
    if (wid == 0) {
        const int b0 = lane * (NB / 32);
        int c[NB / 32];
        int run = 0;
        #pragma unroll
        for (int k = 0; k < NB / 32; ++k) {
            c[k] = run;
            run += binCnt[b0 + k];
        }
        int v = run;
        #pragma unroll
        for (int off = 1; off < 32; off <<= 1) {
            int n = __shfl_up_sync(0xffffffffu, v, off);
            if (lane >= off) v += n;
        }
        const int pre = v - run;
        #pragma unroll
        for (int k = 0; k < NB / 32; ++k) {
            const int s = pre + c[k];
            binStart[b0 + k] = s;
            binFill[b0 + k]  = s;
        }
        if (lane == 31) binStart[NB] = pre + run;      // == N_PTS
    }
    __syncthreads();                                   // B3

    // ---- Scatter (counting sort by bin; in-bin order arbitrary — keys fix it) ----
    #pragma unroll
    for (int i = tid; i < N_PTS; i += BLOCK_THREADS) {
        const float v = sx[i];
        const int pos = atomicAdd(&binFill[bin_of(v)], 1);
        bpt[pos] = make_float2(v, __int_as_float(i));
    }
    __syncthreads();                                   // B4

    // ---- Per-thread NN search over expanding bin window ----
    const int   p     = base + tid;                    // point index within batch
    const int   limit = (p < N_C) ? (N_C - 1) : p;     // valid candidate: j <= limit
    const float xi    = sx[p];

    // top-2 by exact key = (bits(sqrt_rn(dx*dx)) << 32) | j ; init (+inf, maxidx)
    const ull KEY_INF = ((ull)0x7f800000u << 32) | 0xffffffffu;
    ull k1 = KEY_INF, k2 = KEY_INF;

    const int t0 = bin_of(xi);

    #define SCAN_BIN(T)                                                        \
        {                                                                      \
            const int qe = binStart[(T) + 1];                                  \
            for (int q = binStart[(T)]; q < qe; ++q) {                         \
                const float2 pr = bpt[q];                                      \
                const int j = __float_as_int(pr.y);                            \
                if (j <= limit) {                                              \
                    const float dx   = xi - pr.x;                              \
                    const float dist = __fsqrt_rn(__fmul_rn(dx, dx));          \
                    const ull key = ((ull)__float_as_uint(dist) << 32)         \
                                    | (unsigned int)j;                         \
                    if (key < k1)      { k2 = k1; k1 = key; }                  \
                    else if (key < k2) { k2 = key; }                           \
                }                                                              \
            }                                                                  \
        }

    SCAN_BIN(t0);
    {
        int l = t0 - 1, r = t0 + 1;
        while (true) {
            const float d2v = __uint_as_float((unsigned int)(k2 >> 32)); // +inf until 2 found
            // conservative cushion: covers bin-edge rounding + sqrt rounding ties
            const float thr = d2v + (width * 1e-3f + d2v * 1e-5f);
            const float bl = (l >= 0) ? fmaxf(xi - (XMIN_F + (float)(l + 1) * width), 0.0f)
                                      : __int_as_float(0x7f800000);
            const float br = (r < NB) ? fmaxf((XMIN_F + (float)r * width) - xi, 0.0f)
                                      : __int_as_float(0x7f800000);
            const bool canL = (l >= 0) && (bl <= thr);
            const bool canR = (r < NB) && (br <= thr);
            if (!canL && !canR) break;
            if (canL && (!canR || bl <= br)) { SCAN_BIN(l); --l; }
            else                             { SCAN_BIN(r); ++r; }
        }
    }
    #undef SCAN_BIN

    // ---- Derivative + outputs ----
    float d2out;
    {
        const int nn = (int)(unsigned int)(k2 & 0xffffffffULL);  // argsort[...,1]
        const float xcl  = sx[nn];
        const float ycl  = sy[nn];
        const float xrep = xi - xcl;
        const float yrep = sy[p] - ycl;
        const float nrm  = __fsqrt_rn(__fmul_rn(xrep, xrep));
        const float d    = __fdiv_rn(yrep, __fadd_rn(2e-6f, nrm));
        const bool  clip = (fabsf(d) > 200.0f);
        d2out = clip ? 0.0f : d;
        const float lab = clip ? 0.0f : 1.0f;

        const int g = batch * N_PTS + p;
        out[OFF_YDIFF + g]        = yrep;
        out[OFF_XDIFF + g]        = xrep;
        out[OFF_DOUT + 2 * g]     = d2out;   // raw; normalized by kernel B
        out[OFF_DOUT + 2 * g + 1] = lab;
        out[OFF_XN + g]           = xcl;
        out[OFF_YN + g]           = ycl;
    }

    // ---- Per-warp deterministic partial sums (fixed shuffle order) ----
    {
        double s  = (double)d2out;
        double s2 = s * s;
        #pragma unroll
        for (int off = 16; off > 0; off >>= 1) {
            s  += __shfl_down_sync(0xffffffffu, s,  off);
            s2 += __shfl_down_sync(0xffffffffu, s2, off);
        }
        if (lane == 0) {
            const int w = blockIdx.x * 8 + wid;
            g_psum[w]  = s;
            g_psum2[w] = s2;
        }
    }
}

// ---------------- Kernel B: redundant-per-block affine + normalize ------------
// Each of 128 blocks reduces all 512 psum pairs in the SAME fixed order
// (deterministic, identical result in every block), then normalizes its slice.
__global__ __launch_bounds__(128) void bn_kernel(
    const float* __restrict__ bn_w, const float* __restrict__ bn_b,
    float* __restrict__ out)
{
    __shared__ double s_w[4], s_w2[4];
    __shared__ float  s_affine[2];

    const int tid  = threadIdx.x;
    const int wid  = tid >> 5;
    const int lane = tid & 31;

    // Thread t sums entries t, t+128, t+256, t+384 (fixed order).
    double s  = ((g_psum[tid]  + g_psum[tid + 128])  + g_psum[tid + 256])  + g_psum[tid + 384];
    double s2 = ((g_psum2[tid] + g_psum2[tid + 128]) + g_psum2[tid + 256]) + g_psum2[tid + 384];
    #pragma unroll
    for (int off = 16; off > 0; off >>= 1) {
        s  += __shfl_down_sync(0xffffffffu, s,  off);
        s2 += __shfl_down_sync(0xffffffffu, s2, off);
    }
    if (lane == 0) { s_w[wid] = s; s_w2[wid] = s2; }
    __syncthreads();
    if (tid == 0) {
        const double ts  = ((s_w[0] + s_w[1]) + s_w[2]) + s_w[3];
        const double ts2 = ((s_w2[0] + s_w2[1]) + s_w2[2]) + s_w2[3];
        const double n    = (double)N_TOTAL;
        const double mean = ts / n;
        const double var  = ts2 / n - mean * mean;
        const double invs = 1.0 / sqrt(var + 1e-5);
        const float scale = (float)invs * bn_w[0];
        s_affine[0] = scale;
        s_affine[1] = bn_b[0] - (float)mean * scale;
    }
    __syncthreads();

    const int g = blockIdx.x * 128 + tid;              // 128 blocks x 128 = 16384
    const int idx = OFF_DOUT + 2 * g;
    out[idx] = fmaf(out[idx], s_affine[0], s_affine[1]);
}

extern "C" void kernel_launch(void* const* d_in, const int* in_sizes, int n_in,
                              void* d_out, int out_size) {
    const float* y    = (const float*)d_in[0];
    const float* x    = (const float*)d_in[1];
    const float* bn_w = (const float*)d_in[2];
    const float* bn_b = (const float*)d_in[3];
    float* out = (float*)d_out;

    nn_bin_kernel<<<NUM_BLOCKS, BLOCK_THREADS>>>(y, x, out);
    bn_kernel<<<128, 128>>>(bn_w, bn_b, out);
}

// round 10
// speedup vs baseline: 1.7500x; 1.0595x over previous
#include <cuda_runtime.h>

// Problem constants (fixed by setup_inputs)
#define N_PTS 2048
#define N_C   1024
#define B_SZ  8
#define BLOCK_THREADS 256
#define PTS_PER_BLOCK 256
#define BLOCKS_PER_BATCH (N_PTS / PTS_PER_BLOCK)   // 8
#define NUM_BLOCKS (B_SZ * BLOCKS_PER_BATCH)       // 64
#define N_TOTAL (B_SZ * N_PTS)                     // 16384
#define NB 512                                     // bins per batch
#define XMIN_F (-4.5f)
#define XRANGE_F (9.0f)
#define N_PSUM (NUM_BLOCKS * 8)                    // 512 per-warp partials

// Output layout (tuple concat): y_diff | x_diff | d_out(B,N,2) | x_n | y_n
#define OFF_YDIFF 0
#define OFF_XDIFF (N_TOTAL)
#define OFF_DOUT  (2 * N_TOTAL)
#define OFF_XN    (4 * N_TOTAL)
#define OFF_YN    (5 * N_TOTAL)

__device__ float2 g_psumv[N_PSUM];   // (sum, sumsq) per warp

typedef unsigned long long ull;

static __device__ __forceinline__ int bin_of(float v) {
    int t = (int)((v - XMIN_F) * ((float)NB / XRANGE_F));
    t = t < 0 ? 0 : t;
    return t > (NB - 1) ? (NB - 1) : t;
}

// ---------------- Kernel A: binned NN + derivative + outputs + warp psums ----
__global__ __launch_bounds__(BLOCK_THREADS) void nn_bin_kernel(
    const float* __restrict__ y, const float* __restrict__ x,
    float* __restrict__ out)
{
    __shared__ float  sx[N_PTS];
    __shared__ float  sy[N_PTS];
    __shared__ float2 bpt[N_PTS];            // (x value, idx bits) in bin order
    __shared__ int    binCnt[NB];
    __shared__ int    binStart[NB + 1];
    __shared__ int    binFill[NB];

    const int tid   = threadIdx.x;
    const int wid   = tid >> 5;
    const int lane  = tid & 31;
    const int batch = blockIdx.x >> 3;                 // / BLOCKS_PER_BATCH
    const int base  = (blockIdx.x & 7) * PTS_PER_BLOCK;

    const float width = XRANGE_F / (float)NB;

    // ---- Load batch into SMEM, keeping x values in registers ----
    float4 xa, xb;   // this thread's 8 x-values: indices 4*tid..+3, 4*(tid+256)..+3
    {
        const float4* xb4 = (const float4*)(x + batch * N_PTS);
        const float4* yb4 = (const float4*)(y + batch * N_PTS);
        float4* sxv = (float4*)sx;
        float4* syv = (float4*)sy;
        xa = xb4[tid];
        xb = xb4[tid + 256];
        const float4 ya = yb4[tid];
        const float4 yb_ = yb4[tid + 256];
        sxv[tid]       = xa;
        sxv[tid + 256] = xb;
        syv[tid]       = ya;
        syv[tid + 256] = yb_;
    }
    #pragma unroll
    for (int i = tid; i < NB; i += BLOCK_THREADS) binCnt[i] = 0;
    __syncthreads();                                   // B1

    // ---- Histogram from registers (8 points per thread) ----
    atomicAdd(&binCnt[bin_of(xa.x)], 1);
    atomicAdd(&binCnt[bin_of(xa.y)], 1);
    atomicAdd(&binCnt[bin_of(xa.z)], 1);
    atomicAdd(&binCnt[bin_of(xa.w)], 1);
    atomicAdd(&binCnt[bin_of(xb.x)], 1);
    atomicAdd(&binCnt[bin_of(xb.y)], 1);
    atomicAdd(&binCnt[bin_of(xb.z)], 1);
    atomicAdd(&binCnt[bin_of(xb.w)], 1);
    __syncthreads();                                   // B2

    // ---- Exclusive scan over NB=512 bins by warp 0 (16 bins/lane, shuffle scan) ----
    if (wid == 0) {
        const int b0 = lane * (NB / 32);
        int c[NB / 32];
        int run = 0;
        #pragma unroll
        for (int k = 0; k < NB / 32; ++k) {
            c[k] = run;
            run += binCnt[b0 + k];
        }
        int v = run;
        #pragma unroll
        for (int off = 1; off < 32; off <<= 1) {
            int n = __shfl_up_sync(0xffffffffu, v, off);
            if (lane >= off) v += n;
        }
        const int pre = v - run;
        #pragma unroll
        for (int k = 0; k < NB / 32; ++k) {
            const int s = pre + c[k];
            binStart[b0 + k] = s;
            binFill[b0 + k]  = s;
        }
        if (lane == 31) binStart[NB] = pre + run;      // == N_PTS
    }
    __syncthreads();                                   // B3

    // ---- Scatter from registers (counting sort; in-bin order arbitrary) ----
    {
        const int i0 = 4 * tid;
        const int i1 = 4 * (tid + 256);
        int pos;
        pos = atomicAdd(&binFill[bin_of(xa.x)], 1); bpt[pos] = make_float2(xa.x, __int_as_float(i0));
        pos = atomicAdd(&binFill[bin_of(xa.y)], 1); bpt[pos] = make_float2(xa.y, __int_as_float(i0 + 1));
        pos = atomicAdd(&binFill[bin_of(xa.z)], 1); bpt[pos] = make_float2(xa.z, __int_as_float(i0 + 2));
        pos = atomicAdd(&binFill[bin_of(xa.w)], 1); bpt[pos] = make_float2(xa.w, __int_as_float(i0 + 3));
        pos = atomicAdd(&binFill[bin_of(xb.x)], 1); bpt[pos] = make_float2(xb.x, __int_as_float(i1));
        pos = atomicAdd(&binFill[bin_of(xb.y)], 1); bpt[pos] = make_float2(xb.y, __int_as_float(i1 + 1));
        pos = atomicAdd(&binFill[bin_of(xb.z)], 1); bpt[pos] = make_float2(xb.z, __int_as_float(i1 + 2));
        pos = atomicAdd(&binFill[bin_of(xb.w)], 1); bpt[pos] = make_float2(xb.w, __int_as_float(i1 + 3));
    }
    __syncthreads();                                   // B4

    // ---- Per-thread NN search over expanding bin window ----
    const int   p     = base + tid;                    // point index within batch
    const int   limit = (p < N_C) ? (N_C - 1) : p;     // valid candidate: j <= limit
    const float xi    = sx[p];

    // top-2 by exact key = (bits(sqrt_rn(dx*dx)) << 32) | j ; init (+inf, maxidx)
    const ull KEY_INF = ((ull)0x7f800000u << 32) | 0xffffffffu;
    ull k1 = KEY_INF, k2 = KEY_INF;

    const int t0 = bin_of(xi);

    #define SCAN_BIN(T)                                                        \
        {                                                                      \
            const int qe = binStart[(T) + 1];                                  \
            for (int q = binStart[(T)]; q < qe; ++q) {                         \
                const float2 pr = bpt[q];                                      \
                const int j = __float_as_int(pr.y);                            \
                if (j <= limit) {                                              \
                    const float dx   = xi - pr.x;                              \
                    const float dist = __fsqrt_rn(__fmul_rn(dx, dx));          \
                    const ull key = ((ull)__float_as_uint(dist) << 32)         \
                                    | (unsigned int)j;                         \
                    if (key < k1)      { k2 = k1; k1 = key; }                  \
                    else if (key < k2) { k2 = key; }                           \
                }                                                              \
            }                                                                  \
        }

    SCAN_BIN(t0);
    {
        int l = t0 - 1, r = t0 + 1;
        while (true) {
            const float d2v = __uint_as_float((unsigned int)(k2 >> 32)); // +inf until 2 found
            // conservative cushion: covers bin-edge rounding + sqrt rounding ties
            const float thr = d2v + (width * 1e-3f + d2v * 1e-5f);
            const float bl = (l >= 0) ? fmaxf(xi - (XMIN_F + (float)(l + 1) * width), 0.0f)
                                      : __int_as_float(0x7f800000);
            const float br = (r < NB) ? fmaxf((XMIN_F + (float)r * width) - xi, 0.0f)
                                      : __int_as_float(0x7f800000);
            const bool canL = (l >= 0) && (bl <= thr);
            const bool canR = (r < NB) && (br <= thr);
            if (!canL && !canR) break;
            if (canL && (!canR || bl <= br)) { SCAN_BIN(l); --l; }
            else                             { SCAN_BIN(r); ++r; }
        }
    }
    #undef SCAN_BIN

    // ---- Derivative + outputs ----
    float d2out;
    {
        const int nn = (int)(unsigned int)(k2 & 0xffffffffULL);  // argsort[...,1]
        const float xcl  = sx[nn];
        const float ycl  = sy[nn];
        const float xrep = xi - xcl;
        const float yrep = sy[p] - ycl;
        const float nrm  = __fsqrt_rn(__fmul_rn(xrep, xrep));
        const float d    = __fdiv_rn(yrep, __fadd_rn(2e-6f, nrm));
        const bool  clip = (fabsf(d) > 200.0f);
        d2out = clip ? 0.0f : d;
        const float lab = clip ? 0.0f : 1.0f;

        const int g = batch * N_PTS + p;
        out[OFF_YDIFF + g]        = yrep;
        out[OFF_XDIFF + g]        = xrep;
        out[OFF_DOUT + 2 * g]     = d2out;   // raw; normalized by kernel B
        out[OFF_DOUT + 2 * g + 1] = lab;
        out[OFF_XN + g]           = xcl;
        out[OFF_YN + g]           = ycl;
    }

    // ---- Per-warp deterministic partial sums (float, fixed shuffle order) ----
    {
        float s  = d2out;
        float s2 = d2out * d2out;
        #pragma unroll
        for (int off = 16; off > 0; off >>= 1) {
            s  += __shfl_down_sync(0xffffffffu, s,  off);
            s2 += __shfl_down_sync(0xffffffffu, s2, off);
        }
        if (lane == 0)
            g_psumv[blockIdx.x * 8 + wid] = make_float2(s, s2);
    }
}

// ---------------- Kernel B: single-round-trip affine + normalize --------------
// All loads (out slot, 4 psum float2s, bn params) issued up front in parallel;
// fixed-order reduction -> deterministic, identical in every block.
__global__ __launch_bounds__(128) void bn_kernel(
    const float* __restrict__ bn_w, const float* __restrict__ bn_b,
    float* __restrict__ out)
{
    __shared__ float s_w[4], s_w2[4];
    __shared__ float s_affine[2];

    const int tid  = threadIdx.x;
    const int wid  = tid >> 5;
    const int lane = tid & 31;

    const int g   = blockIdx.x * 128 + tid;            // 128 blocks x 128 = 16384
    const int idx = OFF_DOUT + 2 * g;

    // Parallel loads (one memory round-trip)
    const float  oval = out[idx];
    const float2 a = g_psumv[tid];
    const float2 b = g_psumv[tid + 128];
    const float2 c = g_psumv[tid + 256];
    const float2 d = g_psumv[tid + 384];
    const float  w  = bn_w[0];
    const float  bb = bn_b[0];

    float s  = ((a.x + b.x) + c.x) + d.x;
    float s2 = ((a.y + b.y) + c.y) + d.y;
    #pragma unroll
    for (int off = 16; off > 0; off >>= 1) {
        s  += __shfl_down_sync(0xffffffffu, s,  off);
        s2 += __shfl_down_sync(0xffffffffu, s2, off);
    }
    if (lane == 0) { s_w[wid] = s; s_w2[wid] = s2; }
    __syncthreads();
    if (tid == 0) {
        const double ts   = ((double)s_w[0] + s_w[1]) + ((double)s_w[2] + s_w[3]);
        const double ts2  = ((double)s_w2[0] + s_w2[1]) + ((double)s_w2[2] + s_w2[3]);
        const double n    = (double)N_TOTAL;
        const double mean = ts / n;
        const double var  = ts2 / n - mean * mean;
        const double invs = 1.0 / sqrt(var + 1e-5);
        const float scale = (float)invs * w;
        s_affine[0] = scale;
        s_affine[1] = bb - (float)mean * scale;
    }
    __syncthreads();

    out[idx] = fmaf(oval, s_affine[0], s_affine[1]);
}

extern "C" void kernel_launch(void* const* d_in, const int* in_sizes, int n_in,
                              void* d_out, int out_size) {
    const float* y    = (const float*)d_in[0];
    const float* x    = (const float*)d_in[1];
    const float* bn_w = (const float*)d_in[2];
    const float* bn_b = (const float*)d_in[3];
    float* out = (float*)d_out;

    nn_bin_kernel<<<NUM_BLOCKS, BLOCK_THREADS>>>(y, x, out);
    bn_kernel<<<128, 128>>>(bn_w, bn_b, out);
}